// round 4
// baseline (speedup 1.0000x reference)
#include <cuda_runtime.h>
#include <cuda_bf16.h>

typedef unsigned long long ull;

// Problem constants
#define BB   2
#define SS   2048
#define PP   1024
#define DD   2048
#define HH   16
#define DH   128
#define PSL  3072          // P + S
#define MM   4096          // B * S

// ---------------------------------------------------------------------------
// Scratch (device globals; no allocation allowed in kernel_launch)
// ---------------------------------------------------------------------------
__device__ float g_Q[(size_t)BB * HH * SS * DH];      // [b,h,s,d]
__device__ float g_K[(size_t)BB * HH * DH * PSL];     // [b,h,d,j]  (transposed!)
__device__ float g_V[(size_t)BB * HH * PSL * DH];     // [b,h,j,d]
__device__ float g_attn[(size_t)MM * DD];             // [m, h*DH+d]
__device__ float g_loraQKV[(size_t)MM * 48];          // [m, 48] (q|k|v)
__device__ float g_loraO[(size_t)MM * 16];            // [m, 16]

// ---------------------------------------------------------------------------
// Packed f32x2 helpers (FFMA2 — PTX-only on sm_103a, 2x fp32 FMA throughput)
// ---------------------------------------------------------------------------
__device__ __forceinline__ ull pack2(float lo, float hi) {
    ull r; asm("mov.b64 %0, {%1, %2};" : "=l"(r) : "f"(lo), "f"(hi)); return r;
}
__device__ __forceinline__ void unpack2(float& lo, float& hi, ull v) {
    asm("mov.b64 {%0, %1}, %2;" : "=f"(lo), "=f"(hi) : "l"(v));
}
__device__ __forceinline__ void ffma2(ull& d, ull a, ull b) {
    asm("fma.rn.f32x2 %0, %1, %2, %0;" : "+l"(d) : "l"(a), "l"(b));
}
__device__ __forceinline__ void fmul2(ull& d, ull a) {
    asm("mul.rn.f32x2 %0, %0, %1;" : "+l"(d) : "l"(a));
}

// ---------------------------------------------------------------------------
// Kernel 1: LoRA down-projection for q,k,v:  g_loraQKV[m, 0:48] = x @ [wqA|wkA|wvA]
// ---------------------------------------------------------------------------
__global__ __launch_bounds__(256)
void lora_down_qkv(const float* __restrict__ x,
                   const float* __restrict__ wqA,
                   const float* __restrict__ wkA,
                   const float* __restrict__ wvA)
{
    __shared__ float xs[32][36];
    __shared__ float ws[32][48];
    const int tid = threadIdx.x;
    const int m0  = blockIdx.x * 32;
    const int r   = tid >> 3;          // row 0..31
    const int cb  = (tid & 7) * 6;     // 6 cols per thread

    float acc[6] = {0.f, 0.f, 0.f, 0.f, 0.f, 0.f};

    for (int k0 = 0; k0 < DD; k0 += 32) {
        float4 v = *(const float4*)&x[(size_t)(m0 + (tid >> 3)) * DD + k0 + (tid & 7) * 4];
        *(float4*)&xs[tid >> 3][(tid & 7) * 4] = v;
        for (int idx = tid; idx < 32 * 48; idx += 256) {
            int kk = idx / 48, c = idx % 48;
            const float* w = (c < 16) ? wqA : ((c < 32) ? wkA : wvA);
            ws[kk][c] = w[(size_t)(k0 + kk) * 16 + (c & 15)];
        }
        __syncthreads();
#pragma unroll
        for (int kk = 0; kk < 32; kk++) {
            float a = xs[r][kk];
#pragma unroll
            for (int c = 0; c < 6; c++) acc[c] += a * ws[kk][cb + c];
        }
        __syncthreads();
    }
#pragma unroll
    for (int c = 0; c < 6; c++) g_loraQKV[(size_t)(m0 + r) * 48 + cb + c] = acc[c];
}

// ---------------------------------------------------------------------------
// Kernel 1b: LoRA down for output path: g_loraO = g_attn @ woA
// ---------------------------------------------------------------------------
__global__ __launch_bounds__(256)
void lora_down_o(const float* __restrict__ woA)
{
    __shared__ float xs[32][36];
    __shared__ float ws[32][16];
    const int tid = threadIdx.x;
    const int m0  = blockIdx.x * 32;
    const int r   = tid >> 3;
    const int cb  = (tid & 7) * 2;

    float acc[2] = {0.f, 0.f};

    for (int k0 = 0; k0 < DD; k0 += 32) {
        float4 v = *(const float4*)&g_attn[(size_t)(m0 + (tid >> 3)) * DD + k0 + (tid & 7) * 4];
        *(float4*)&xs[tid >> 3][(tid & 7) * 4] = v;
        for (int idx = tid; idx < 32 * 16; idx += 256) {
            int kk = idx >> 4, c = idx & 15;
            ws[kk][c] = woA[(size_t)(k0 + kk) * 16 + c];
        }
        __syncthreads();
#pragma unroll
        for (int kk = 0; kk < 32; kk++) {
            float a = xs[r][kk];
            acc[0] += a * ws[kk][cb + 0];
            acc[1] += a * ws[kk][cb + 1];
        }
        __syncthreads();
    }
    g_loraO[(size_t)(m0 + r) * 16 + cb + 0] = acc[0];
    g_loraO[(size_t)(m0 + r) * 16 + cb + 1] = acc[1];
}

// ---------------------------------------------------------------------------
// Kernel 2: scatter prev_key/prev_value into attention layouts
// ---------------------------------------------------------------------------
__global__ void scatter_prev(const float* __restrict__ pk, const float* __restrict__ pv)
{
    int idx = blockIdx.x * blockDim.x + threadIdx.x;   // over B*P*H*(DH/4)
    if (idx >= BB * PP * HH * (DH / 4)) return;
    int d4 = idx & 31;
    int h  = (idx >> 5) & 15;
    int p  = (idx >> 9) & 1023;
    int b  = idx >> 19;

    float4 v = *(const float4*)&pv[(size_t)idx * 4];
    *(float4*)&g_V[(((size_t)(b * HH + h) * PSL) + p) * DH + d4 * 4] = v;

    float4 kq = *(const float4*)&pk[(size_t)idx * 4];
    float* kd = &g_K[((size_t)(b * HH + h) * DH + d4 * 4) * PSL + p];
    kd[0 * PSL] = kq.x; kd[1 * PSL] = kq.y; kd[2 * PSL] = kq.z; kd[3 * PSL] = kq.w;
}

// ---------------------------------------------------------------------------
// Kernel 3: 128x128x8 GEMM with LoRA K-extension + RoPE/scatter epilogue
//   C[m,n] = sum_k A[m,k]*W[n,k] + ps[b] * sum_r aL[m,r]*wB[r,n]
//   mode 0: q (RoPE -> g_Q)   mode 1: k (RoPE -> g_K transposed)
//   mode 2: v (-> g_V)        mode 3: o (-> Cout)
// ---------------------------------------------------------------------------
__device__ __forceinline__ void mma_tile8(ull acc[8][4], const float* As, const float* Bs,
                                          int ty, int tx)
{
#pragma unroll
    for (int kk = 0; kk < 8; kk++) {
        const float4 a0 = *(const float4*)&As[kk * 128 + ty * 8];
        const float4 a1 = *(const float4*)&As[kk * 128 + ty * 8 + 4];
        const longlong2 bq0 = *(const longlong2*)&Bs[kk * 128 + tx * 8];
        const longlong2 bq1 = *(const longlong2*)&Bs[kk * 128 + tx * 8 + 4];
        ull aa[8];
        aa[0] = pack2(a0.x, a0.x); aa[1] = pack2(a0.y, a0.y);
        aa[2] = pack2(a0.z, a0.z); aa[3] = pack2(a0.w, a0.w);
        aa[4] = pack2(a1.x, a1.x); aa[5] = pack2(a1.y, a1.y);
        aa[6] = pack2(a1.z, a1.z); aa[7] = pack2(a1.w, a1.w);
        const ull b0 = (ull)bq0.x, b1 = (ull)bq0.y, b2 = (ull)bq1.x, b3 = (ull)bq1.y;
#pragma unroll
        for (int i = 0; i < 8; i++) {
            ffma2(acc[i][0], aa[i], b0);
            ffma2(acc[i][1], aa[i], b1);
            ffma2(acc[i][2], aa[i], b2);
            ffma2(acc[i][3], aa[i], b3);
        }
    }
}

__global__ __launch_bounds__(256, 2)
void gemm_proj(const float* __restrict__ Ain,
               const float* __restrict__ W0, const float* __restrict__ W1,
               const float* __restrict__ W2,
               const float* __restrict__ B0, const float* __restrict__ B1,
               const float* __restrict__ B2,
               const float* __restrict__ psc,
               const float* __restrict__ fcos, const float* __restrict__ fsin,
               float* __restrict__ Cout, int is_o)
{
    __shared__ __align__(16) float As[8 * 128];
    __shared__ __align__(16) float Bs[8 * 128];

    const int tid  = threadIdx.x;
    const int m0   = blockIdx.y * 128;
    const int n0   = blockIdx.x * 128;
    const int mode = is_o ? 3 : blockIdx.z;

    const float* A  = is_o ? g_attn : Ain;
    const float* W  = (mode == 0 || mode == 3) ? W0 : ((mode == 1) ? W1 : W2);
    const float* wB = (mode == 0 || mode == 3) ? B0 : ((mode == 1) ? B1 : B2);
    const float* aL = is_o ? g_loraO : g_loraQKV;
    const int aLs   = is_o ? 16 : 48;
    const int aLo   = is_o ? 0 : mode * 16;

    const int lr = tid >> 1;
    const int lc = (tid & 1) * 4;
    const int tx = tid & 15, ty = tid >> 4;

    ull acc[8][4];
#pragma unroll
    for (int i = 0; i < 8; i++)
#pragma unroll
        for (int j = 0; j < 4; j++) acc[i][j] = 0ull;

    const float* Aptr = A + (size_t)(m0 + lr) * DD + lc;
    const float* Wptr = W + (size_t)(n0 + lr) * DD + lc;

    for (int k0 = 0; k0 < DD; k0 += 8) {
        float4 av = *(const float4*)(Aptr + k0);
        float4 bv = *(const float4*)(Wptr + k0);
        As[(lc + 0) * 128 + lr] = av.x; As[(lc + 1) * 128 + lr] = av.y;
        As[(lc + 2) * 128 + lr] = av.z; As[(lc + 3) * 128 + lr] = av.w;
        Bs[(lc + 0) * 128 + lr] = bv.x; Bs[(lc + 1) * 128 + lr] = bv.y;
        Bs[(lc + 2) * 128 + lr] = bv.z; Bs[(lc + 3) * 128 + lr] = bv.w;
        __syncthreads();
        mma_tile8(acc, As, Bs, ty, tx);
        __syncthreads();
    }

    // LoRA as 2 extra virtual K-tiles (R=16); ps folded into A'
    const float psv = psc[(m0 + lr) >> 11];
#pragma unroll
    for (int t = 0; t < 2; t++) {
        const float* ap = aL + (size_t)(m0 + lr) * aLs + aLo + t * 8 + lc;
        As[(lc + 0) * 128 + lr] = ap[0] * psv;
        As[(lc + 1) * 128 + lr] = ap[1] * psv;
        As[(lc + 2) * 128 + lr] = ap[2] * psv;
        As[(lc + 3) * 128 + lr] = ap[3] * psv;
        int r2 = tid >> 5, nn = (tid & 31) * 4;
        float4 bv = *(const float4*)&wB[(size_t)(t * 8 + r2) * DD + n0 + nn];
        *(float4*)&Bs[r2 * 128 + nn] = bv;
        __syncthreads();
        mma_tile8(acc, As, Bs, ty, tx);
        __syncthreads();
    }

    // Unpack
    float c[8][8];
#pragma unroll
    for (int i = 0; i < 8; i++)
#pragma unroll
        for (int j = 0; j < 4; j++) unpack2(c[i][2 * j], c[i][2 * j + 1], acc[i][j]);

    const int mbase = m0 + ty * 8;
    const int nbase = n0 + tx * 8;

    if (mode == 3) {
#pragma unroll
        for (int i = 0; i < 8; i++) {
            float* dst = &Cout[(size_t)(mbase + i) * DD + nbase];
            *(float4*)dst       = make_float4(c[i][0], c[i][1], c[i][2], c[i][3]);
            *(float4*)(dst + 4) = make_float4(c[i][4], c[i][5], c[i][6], c[i][7]);
        }
        return;
    }

    const int h  = nbase >> 7;
    const int d0 = nbase & 127;   // all 8 cols within one head

    if (mode == 2) {
#pragma unroll
        for (int i = 0; i < 8; i++) {
            int m = mbase + i, b = m >> 11, s = m & 2047;
            float* dst = &g_V[(((size_t)(b * HH + h) * PSL) + PP + s) * DH + d0];
            *(float4*)dst       = make_float4(c[i][0], c[i][1], c[i][2], c[i][3]);
            *(float4*)(dst + 4) = make_float4(c[i][4], c[i][5], c[i][6], c[i][7]);
        }
        return;
    }

    // RoPE for q/k
#pragma unroll
    for (int i = 0; i < 8; i++) {
        int m = mbase + i, b = m >> 11, s = m & 2047;
        const float* cp = &fcos[s * 64 + (d0 >> 1)];
        const float* sp = &fsin[s * 64 + (d0 >> 1)];
        float e[4], o[4];
#pragma unroll
        for (int j2 = 0; j2 < 4; j2++) {
            float a = c[i][2 * j2], bq = c[i][2 * j2 + 1];
            float cz = cp[j2], sz = sp[j2];
            e[j2] = a * cz - bq * sz;
            o[j2] = a * sz + bq * cz;
        }
        if (mode == 0) {
            float* dst = &g_Q[(((size_t)(b * HH + h) * SS) + s) * DH + d0];
            *(float4*)dst       = make_float4(e[0], o[0], e[1], o[1]);
            *(float4*)(dst + 4) = make_float4(e[2], o[2], e[3], o[3]);
        } else {
            // transposed K layout [b,h,d,j], j = P + s
            float* dst = &g_K[((size_t)(b * HH + h) * DH + d0) * PSL + PP + s];
#pragma unroll
            for (int j2 = 0; j2 < 4; j2++) {
                dst[(2 * j2) * PSL]     = e[j2];
                dst[(2 * j2 + 1) * PSL] = o[j2];
            }
        }
    }
}

// ---------------------------------------------------------------------------
// Kernel 4: flash attention, fp32, 64x64 tiles, online softmax
// ---------------------------------------------------------------------------
#define ATTN_SMEM ((64 * 128 + 128 * 68 + 64 * 68 + 64 * 3) * 4)

__global__ __launch_bounds__(256, 2)
void attn_kernel()
{
    extern __shared__ __align__(16) float sm[];
    float* Qs   = sm;                     // [64][128]
    float* Kst  = Qs + 64 * 128;          // [128][68] (Kt) aliased with Vs[64][128]
    float* Ss   = Kst + 128 * 68;         // [64][68]
    float* mrow = Ss + 64 * 68;
    float* lrow = mrow + 64;
    float* arow = lrow + 64;

    const int tid = threadIdx.x;
    const int bh  = blockIdx.y;           // b*16 + h
    const int i0  = blockIdx.x * 64;      // query tile start
    const int tx  = tid & 15, ty = tid >> 4;

    const float* Qb = g_Q + (size_t)bh * SS * DH;
    const float* Kb = g_K + (size_t)bh * DH * PSL;
    const float* Vb = g_V + (size_t)bh * PSL * DH;

    const float scl = 0.088388347648318447f;   // 1/sqrt(128)
    for (int idx = tid; idx < 64 * 32; idx += 256) {
        int rr = idx >> 5, c4 = idx & 31;
        float4 v = *(const float4*)&Qb[(size_t)(i0 + rr) * DH + c4 * 4];
        v.x *= scl; v.y *= scl; v.z *= scl; v.w *= scl;
        *(float4*)&Qs[rr * 128 + c4 * 4] = v;
    }
    if (tid < 64) { mrow[tid] = -1e30f; lrow[tid] = 0.f; }

    ull o2[4][4];
#pragma unroll
    for (int i = 0; i < 4; i++)
#pragma unroll
        for (int j = 0; j < 4; j++) o2[i][j] = 0ull;

    const int ntiles = 17 + (i0 >> 6);
    const int srow = tid >> 2, l4 = tid & 3;

    for (int t = 0; t < ntiles; t++) {
        const int j0 = t * 64;
        __syncthreads();   // protect aliased K/V buffer from previous iteration

        // Load K^T tile [128 d][64 j] (coalesced, K stored d-major)
        for (int idx = tid; idx < 128 * 16; idx += 256) {
            int dd = idx >> 4, j4 = idx & 15;
            float4 v = *(const float4*)&Kb[(size_t)dd * PSL + j0 + j4 * 4];
            *(float4*)&Kst[dd * 68 + j4 * 4] = v;
        }
        __syncthreads();

        // S = Q K^T  (4 rows x 4 keys per thread, packed f32x2 over keys)
        ull s2[4][2];
#pragma unroll
        for (int i = 0; i < 4; i++) { s2[i][0] = 0ull; s2[i][1] = 0ull; }
#pragma unroll 8
        for (int kk = 0; kk < 128; kk++) {
            longlong2 bq = *(const longlong2*)&Kst[kk * 68 + tx * 4];
            const ull b0 = (ull)bq.x, b1 = (ull)bq.y;
#pragma unroll
            for (int i = 0; i < 4; i++) {
                float a = Qs[(ty * 4 + i) * 128 + kk];
                ull aa = pack2(a, a);
                ffma2(s2[i][0], aa, b0);
                ffma2(s2[i][1], aa, b1);
            }
        }

        // mask + store scores
#pragma unroll
        for (int i = 0; i < 4; i++) {
            int jlim = PP + i0 + ty * 4 + i;   // keys j <= jlim are valid
#pragma unroll
            for (int jj = 0; jj < 2; jj++) {
                float lo, hi;
                unpack2(lo, hi, s2[i][jj]);
                int j = j0 + tx * 4 + jj * 2;
                if (j > jlim)     lo = -1e30f;
                if (j + 1 > jlim) hi = -1e30f;
                Ss[(ty * 4 + i) * 68 + tx * 4 + jj * 2]     = lo;
                Ss[(ty * 4 + i) * 68 + tx * 4 + jj * 2 + 1] = hi;
            }
        }
        __syncthreads();

        // online softmax: 4 threads per row
        {
            float* srp = &Ss[srow * 68 + l4 * 16];
            float mt = -1e30f;
#pragma unroll
            for (int cc = 0; cc < 16; cc++) mt = fmaxf(mt, srp[cc]);
            mt = fmaxf(mt, __shfl_xor_sync(0xffffffffu, mt, 1));
            mt = fmaxf(mt, __shfl_xor_sync(0xffffffffu, mt, 2));
            float mo = mrow[srow];
            float mn = fmaxf(mo, mt);
            float su = 0.f;
#pragma unroll
            for (int cc = 0; cc < 16; cc++) {
                float p = __expf(srp[cc] - mn);
                srp[cc] = p;
                su += p;
            }
            su += __shfl_xor_sync(0xffffffffu, su, 1);
            su += __shfl_xor_sync(0xffffffffu, su, 2);
            if (l4 == 0) {
                float al = __expf(mo - mn);
                lrow[srow] = lrow[srow] * al + su;
                mrow[srow] = mn;
                arow[srow] = al;
            }
        }
        __syncthreads();

        // Load V tile [64][128] over Kst
        float* Vs = Kst;
        for (int idx = tid; idx < 64 * 32; idx += 256) {
            int rr = idx >> 5, c4 = idx & 31;
            *(float4*)&Vs[rr * 128 + c4 * 4] =
                *(const float4*)&Vb[(size_t)(j0 + rr) * DH + c4 * 4];
        }
        __syncthreads();

        // rescale + PV accumulate (4 rows x 8 d-cols per thread)
#pragma unroll
        for (int i = 0; i < 4; i++) {
            float al = arow[ty * 4 + i];
            ull af = pack2(al, al);
#pragma unroll
            for (int j = 0; j < 4; j++) fmul2(o2[i][j], af);
        }
#pragma unroll 4
        for (int jk = 0; jk < 64; jk++) {
            longlong2 v0 = *(const longlong2*)&Vs[jk * 128 + tx * 8];
            longlong2 v1 = *(const longlong2*)&Vs[jk * 128 + tx * 8 + 4];
            const ull b0 = (ull)v0.x, b1 = (ull)v0.y, b2 = (ull)v1.x, b3 = (ull)v1.y;
#pragma unroll
            for (int i = 0; i < 4; i++) {
                float p = Ss[(ty * 4 + i) * 68 + jk];
                ull pp = pack2(p, p);
                ffma2(o2[i][0], pp, b0);
                ffma2(o2[i][1], pp, b1);
                ffma2(o2[i][2], pp, b2);
                ffma2(o2[i][3], pp, b3);
            }
        }
    }

    // normalize and write out to [m, h*DH+d]
    const int b = bh >> 4, h = bh & 15;
#pragma unroll
    for (int i = 0; i < 4; i++) {
        int sq = i0 + ty * 4 + i;
        float inv = 1.0f / lrow[ty * 4 + i];
        float o[8];
#pragma unroll
        for (int j = 0; j < 4; j++) {
            unpack2(o[2 * j], o[2 * j + 1], o2[i][j]);
            o[2 * j] *= inv; o[2 * j + 1] *= inv;
        }
        float* dst = &g_attn[((size_t)b * SS + sq) * DD + h * DH + tx * 8];
        *(float4*)dst       = make_float4(o[0], o[1], o[2], o[3]);
        *(float4*)(dst + 4) = make_float4(o[4], o[5], o[6], o[7]);
    }
}

// ---------------------------------------------------------------------------
// Launch
// ---------------------------------------------------------------------------
extern "C" void kernel_launch(void* const* d_in, const int* in_sizes, int n_in,
                              void* d_out, int out_size)
{
    const float* x    = (const float*)d_in[0];
    const float* fcos = (const float*)d_in[1];
    const float* fsin = (const float*)d_in[2];
    // d_in[3] = mask (unused; causality computed analytically)
    const float* pk   = (const float*)d_in[4];
    const float* pv   = (const float*)d_in[5];
    const float* ps   = (const float*)d_in[6];
    const float* wq   = (const float*)d_in[7];
    const float* wk   = (const float*)d_in[8];
    const float* wv   = (const float*)d_in[9];
    const float* wo   = (const float*)d_in[10];
    const float* wqA  = (const float*)d_in[11];
    const float* wqB  = (const float*)d_in[12];
    const float* wkA  = (const float*)d_in[13];
    const float* wkB  = (const float*)d_in[14];
    const float* wvA  = (const float*)d_in[15];
    const float* wvB  = (const float*)d_in[16];
    const float* woA  = (const float*)d_in[17];
    const float* woB  = (const float*)d_in[18];
    float* out        = (float*)d_out;

    cudaFuncSetAttribute(attn_kernel, cudaFuncAttributeMaxDynamicSharedMemorySize,
                         ATTN_SMEM);

    scatter_prev<<<(BB * PP * HH * (DH / 4) + 255) / 256, 256>>>(pk, pv);
    lora_down_qkv<<<MM / 32, 256>>>(x, wqA, wkA, wvA);
    gemm_proj<<<dim3(DD / 128, MM / 128, 3), 256>>>(x, wq, wk, wv, wqB, wkB, wvB,
                                                    ps, fcos, fsin, nullptr, 0);
    attn_kernel<<<dim3(SS / 64, BB * HH), 256, ATTN_SMEM>>>();
    lora_down_o<<<MM / 32, 256>>>(woA);
    gemm_proj<<<dim3(DD / 128, MM / 128, 1), 256>>>(nullptr, wo, nullptr, nullptr,
                                                    woB, nullptr, nullptr,
                                                    ps, fcos, fsin, out, 1);
}

// round 7
// speedup vs baseline: 1.5302x; 1.5302x over previous
#include <cuda_runtime.h>
#include <cuda_bf16.h>
#include <cstdint>

typedef unsigned long long ull;

// Problem constants
#define BB   2
#define SS   2048
#define PP   1024
#define DD   2048
#define HH   16
#define DH   128
#define PSL  3072          // P + S
#define MM   4096          // B * S

// ---------------------------------------------------------------------------
// Scratch (device globals; no allocation allowed in kernel_launch)
// ---------------------------------------------------------------------------
__device__ float g_Q[(size_t)BB * HH * SS * DH];      // [b,h,s,d]
__device__ float g_K[(size_t)BB * HH * DH * PSL];     // [b,h,d,j]  (transposed!)
__device__ float g_V[(size_t)BB * HH * PSL * DH];     // [b,h,j,d]
__device__ float g_attn[(size_t)MM * DD];             // [m, h*DH+d]
__device__ float g_loraQKV[(size_t)MM * 48];          // [m, 48] (q|k|v)
__device__ float g_loraO[(size_t)MM * 16];            // [m, 16]

// bf16 split operands for tensor-core GEMMs
__device__ __nv_bfloat16 g_xhi[(size_t)MM * DD];
__device__ __nv_bfloat16 g_xlo[(size_t)MM * DD];
__device__ __nv_bfloat16 g_ahi[(size_t)MM * DD];
__device__ __nv_bfloat16 g_alo[(size_t)MM * DD];
__device__ __nv_bfloat16 g_whi[(size_t)4 * DD * DD];  // wq|wk|wv|wo
__device__ __nv_bfloat16 g_wlo[(size_t)4 * DD * DD];

// ---------------------------------------------------------------------------
// Packed f32x2 helpers (FFMA2) — used by the SIMT attention kernel
// ---------------------------------------------------------------------------
__device__ __forceinline__ ull pack2(float lo, float hi) {
    ull r; asm("mov.b64 %0, {%1, %2};" : "=l"(r) : "f"(lo), "f"(hi)); return r;
}
__device__ __forceinline__ void unpack2(float& lo, float& hi, ull v) {
    asm("mov.b64 {%0, %1}, %2;" : "=f"(lo), "=f"(hi) : "l"(v));
}
__device__ __forceinline__ void ffma2(ull& d, ull a, ull b) {
    asm("fma.rn.f32x2 %0, %1, %2, %0;" : "+l"(d) : "l"(a), "l"(b));
}
__device__ __forceinline__ void fmul2(ull& d, ull a) {
    asm("mul.rn.f32x2 %0, %0, %1;" : "+l"(d) : "l"(a));
}

// ---------------------------------------------------------------------------
// sm_80-ISA tensor-core helpers (valid for plain sm_103 ptxas target)
// ---------------------------------------------------------------------------
__device__ __forceinline__ uint32_t smem_to_u32(const void* smem_ptr) {
    uint32_t addr;
    asm("{ .reg .u64 tmp; cvta.to.shared.u64 tmp, %1; cvt.u32.u64 %0, tmp; }"
        : "=r"(addr) : "l"(smem_ptr));
    return addr;
}
__device__ __forceinline__ void cp16(uint32_t dst, const void* src) {
    asm volatile("cp.async.cg.shared.global [%0], [%1], 16;"
                 :: "r"(dst), "l"(src) : "memory");
}
#define CP_COMMIT() asm volatile("cp.async.commit_group;" ::: "memory")
#define CP_WAIT1()  asm volatile("cp.async.wait_group 1;" ::: "memory")
#define CP_WAIT0()  asm volatile("cp.async.wait_group 0;" ::: "memory")

__device__ __forceinline__ void ldsm4(uint32_t a[4], uint32_t addr) {
    asm volatile("ldmatrix.sync.aligned.m8n8.x4.shared.b16 {%0,%1,%2,%3}, [%4];"
        : "=r"(a[0]), "=r"(a[1]), "=r"(a[2]), "=r"(a[3]) : "r"(addr));
}
__device__ __forceinline__ void mma16816(float d[4], const uint32_t a[4],
                                         const uint32_t b[2]) {
    asm volatile(
        "mma.sync.aligned.m16n8k16.row.col.f32.bf16.bf16.f32 "
        "{%0,%1,%2,%3}, {%4,%5,%6,%7}, {%8,%9}, {%0,%1,%2,%3};"
        : "+f"(d[0]), "+f"(d[1]), "+f"(d[2]), "+f"(d[3])
        : "r"(a[0]), "r"(a[1]), "r"(a[2]), "r"(a[3]), "r"(b[0]), "r"(b[1]));
}

// ---------------------------------------------------------------------------
// fp32 -> bf16 hi/lo split kernels
// ---------------------------------------------------------------------------
__device__ __forceinline__ void bsplit4_store(float4 v, __nv_bfloat16* hi,
                                              __nv_bfloat16* lo, size_t i4)
{
    float a[4] = {v.x, v.y, v.z, v.w};
    unsigned short h[4], l[4];
#pragma unroll
    for (int j = 0; j < 4; j++) {
        __nv_bfloat16 hb = __float2bfloat16(a[j]);
        float r = a[j] - __bfloat162float(hb);
        __nv_bfloat16 lb = __float2bfloat16(r);
        h[j] = __bfloat16_as_ushort(hb);
        l[j] = __bfloat16_as_ushort(lb);
    }
    ((ushort4*)hi)[i4] = make_ushort4(h[0], h[1], h[2], h[3]);
    ((ushort4*)lo)[i4] = make_ushort4(l[0], l[1], l[2], l[3]);
}

__global__ __launch_bounds__(256)
void split4(const float* __restrict__ src, __nv_bfloat16* __restrict__ hi,
            __nv_bfloat16* __restrict__ lo)
{
    size_t i = (size_t)blockIdx.x * 256 + threadIdx.x;     // over N/4 float4s
    float4 v = ((const float4*)src)[i];
    bsplit4_store(v, hi, lo, i);
}

__global__ __launch_bounds__(256)
void split_w4(const float* __restrict__ w0, const float* __restrict__ w1,
              const float* __restrict__ w2, const float* __restrict__ w3)
{
    const int z = blockIdx.z;
    const float* src = (z == 0) ? w0 : ((z == 1) ? w1 : ((z == 2) ? w2 : w3));
    __nv_bfloat16* hi = g_whi + (size_t)z * DD * DD;
    __nv_bfloat16* lo = g_wlo + (size_t)z * DD * DD;
    size_t i = (size_t)blockIdx.x * 256 + threadIdx.x;
    float4 v = ((const float4*)src)[i];
    bsplit4_store(v, hi, lo, i);
}

// ---------------------------------------------------------------------------
// LoRA down-projections (skinny fp32 GEMMs)
// ---------------------------------------------------------------------------
__global__ __launch_bounds__(256)
void lora_down_qkv(const float* __restrict__ x,
                   const float* __restrict__ wqA,
                   const float* __restrict__ wkA,
                   const float* __restrict__ wvA)
{
    __shared__ float xs[32][36];
    __shared__ float ws[32][48];
    const int tid = threadIdx.x;
    const int m0  = blockIdx.x * 32;
    const int r   = tid >> 3;
    const int cb  = (tid & 7) * 6;

    float acc[6] = {0.f, 0.f, 0.f, 0.f, 0.f, 0.f};

    for (int k0 = 0; k0 < DD; k0 += 32) {
        float4 v = *(const float4*)&x[(size_t)(m0 + (tid >> 3)) * DD + k0 + (tid & 7) * 4];
        *(float4*)&xs[tid >> 3][(tid & 7) * 4] = v;
        for (int idx = tid; idx < 32 * 48; idx += 256) {
            int kk = idx / 48, c = idx % 48;
            const float* w = (c < 16) ? wqA : ((c < 32) ? wkA : wvA);
            ws[kk][c] = w[(size_t)(k0 + kk) * 16 + (c & 15)];
        }
        __syncthreads();
#pragma unroll
        for (int kk = 0; kk < 32; kk++) {
            float a = xs[r][kk];
#pragma unroll
            for (int c = 0; c < 6; c++) acc[c] += a * ws[kk][cb + c];
        }
        __syncthreads();
    }
#pragma unroll
    for (int c = 0; c < 6; c++) g_loraQKV[(size_t)(m0 + r) * 48 + cb + c] = acc[c];
}

__global__ __launch_bounds__(256)
void lora_down_o(const float* __restrict__ woA)
{
    __shared__ float xs[32][36];
    __shared__ float ws[32][16];
    const int tid = threadIdx.x;
    const int m0  = blockIdx.x * 32;
    const int r   = tid >> 3;
    const int cb  = (tid & 7) * 2;

    float acc[2] = {0.f, 0.f};

    for (int k0 = 0; k0 < DD; k0 += 32) {
        float4 v = *(const float4*)&g_attn[(size_t)(m0 + (tid >> 3)) * DD + k0 + (tid & 7) * 4];
        *(float4*)&xs[tid >> 3][(tid & 7) * 4] = v;
        for (int idx = tid; idx < 32 * 16; idx += 256) {
            int kk = idx >> 4, c = idx & 15;
            ws[kk][c] = woA[(size_t)(k0 + kk) * 16 + c];
        }
        __syncthreads();
#pragma unroll
        for (int kk = 0; kk < 32; kk++) {
            float a = xs[r][kk];
            acc[0] += a * ws[kk][cb + 0];
            acc[1] += a * ws[kk][cb + 1];
        }
        __syncthreads();
    }
    g_loraO[(size_t)(m0 + r) * 16 + cb + 0] = acc[0];
    g_loraO[(size_t)(m0 + r) * 16 + cb + 1] = acc[1];
}

// ---------------------------------------------------------------------------
// scatter prev_key/prev_value into attention layouts
// ---------------------------------------------------------------------------
__global__ void scatter_prev(const float* __restrict__ pk, const float* __restrict__ pv)
{
    int idx = blockIdx.x * blockDim.x + threadIdx.x;   // over B*P*H*(DH/4)
    if (idx >= BB * PP * HH * (DH / 4)) return;
    int d4 = idx & 31;
    int h  = (idx >> 5) & 15;
    int p  = (idx >> 9) & 1023;
    int b  = idx >> 19;

    float4 v = *(const float4*)&pv[(size_t)idx * 4];
    *(float4*)&g_V[(((size_t)(b * HH + h) * PSL) + p) * DH + d4 * 4] = v;

    float4 kq = *(const float4*)&pk[(size_t)idx * 4];
    float* kd = &g_K[((size_t)(b * HH + h) * DH + d4 * 4) * PSL + p];
    kd[0 * PSL] = kq.x; kd[1 * PSL] = kq.y; kd[2 * PSL] = kq.z; kd[3 * PSL] = kq.w;
}

// ---------------------------------------------------------------------------
// HMMA GEMM: 128x128 CTA tile, bf16-split (K = 3*2048 virtual), mma.sync,
// cp.async double-buffered.  LoRA rank-16 + RoPE/scatter fp32 epilogue.
//   mode 0: q (RoPE -> g_Q)   mode 1: k (RoPE -> g_K transposed)
//   mode 2: v (-> g_V)        mode 3: o (-> Cout)
// smem layout (byte offsets from 128B-aligned base):
//   mainloop: A tiles [2][16384], B tiles at 32768 + [2][16384]   (64 KB)
//   epilogue: Cst fp32 [128][132] at 0 (67584 B), wBs [16][128] at 67584
// ---------------------------------------------------------------------------
#define GEMM_SMEM (67584 + 8192 + 128)
#define NSTAGE 96

__global__ __launch_bounds__(256)
void gemm_tc(const float* __restrict__ psc,
             const float* __restrict__ fcos, const float* __restrict__ fsin,
             const float* __restrict__ Bq, const float* __restrict__ Bk,
             const float* __restrict__ Bv,
             float* __restrict__ Cout, int is_o)
{
    extern __shared__ __align__(128) char dsm[];
    const uint32_t smem_raw = smem_to_u32(dsm);
    const uint32_t sb = (smem_raw + 127) & ~127u;
    char* sgen = dsm + (sb - smem_raw);

    const int tid  = threadIdx.x;
    const int lane = tid & 31;
    const int w    = tid >> 5;
    const int mode = is_o ? 3 : blockIdx.z;
    const int m0   = blockIdx.y * 128;
    const int n0   = blockIdx.x * 128;

    const __nv_bfloat16* __restrict__ Ahi = is_o ? g_ahi : g_xhi;
    const __nv_bfloat16* __restrict__ Alo = is_o ? g_alo : g_xlo;
    const __nv_bfloat16* __restrict__ Bhi = g_whi + (size_t)mode * DD * DD;
    const __nv_bfloat16* __restrict__ Blo = g_wlo + (size_t)mode * DD * DD;

    // LoRA wB tile -> smem (region disjoint from mainloop tiles)
    float* wBs = (float*)(sgen + 67584);
    const float* wBp = (mode == 0 || mode == 3) ? Bq : ((mode == 1) ? Bk : Bv);
    for (int idx = tid; idx < 16 * 128; idx += 256)
        wBs[idx] = wBp[(idx >> 7) * DD + n0 + (idx & 127)];

    // --- gmem->smem mapping (per thread: 4 rows x 16B for A and B) ---
    const int rb = tid >> 3;                 // base row 0..31 (+32t)
    const int c8 = tid & 7;                  // 16B chunk within 128B row
    const uint32_t dx   = (uint32_t)((c8 ^ (rb & 7)) * 16);  // swizzled col byte
    const uint32_t drow = (uint32_t)(rb * 128);

    // --- warp fragment addressing ---
    const int wm = (w & 1) * 64;
    const int wn = (w >> 1) * 32;
    const int lrow = lane & 15;
    const uint32_t lcol = (uint32_t)((lane >> 4) * 16);
    uint32_t arow[4], amask[4], brow[2], bmask[2];
#pragma unroll
    for (int i = 0; i < 4; i++) {
        int rr = wm + i * 16 + lrow;
        arow[i] = (uint32_t)(rr * 128); amask[i] = (uint32_t)((rr & 7) * 16);
    }
#pragma unroll
    for (int jj = 0; jj < 2; jj++) {
        int rr = wn + jj * 16 + lrow;
        brow[jj] = (uint32_t)(rr * 128); bmask[jj] = (uint32_t)((rr & 7) * 16);
    }

    float d[4][4][4];
#pragma unroll
    for (int i = 0; i < 4; i++)
#pragma unroll
        for (int j = 0; j < 4; j++)
#pragma unroll
            for (int q = 0; q < 4; q++) d[i][j][q] = 0.f;

    auto issue = [&](int s) {
        const int buf = s & 1;
        const int ko  = (s & 31) << 6;
        const __nv_bfloat16* As = (s >= 64) ? Alo : Ahi;
        const __nv_bfloat16* Bs = (s >= 32 && s < 64) ? Blo : Bhi;
        const __nv_bfloat16* ap = As + (size_t)(m0 + rb) * DD + ko + c8 * 8;
        const __nv_bfloat16* bp = Bs + (size_t)(n0 + rb) * DD + ko + c8 * 8;
        const uint32_t da = sb + (uint32_t)(buf * 16384) + drow + dx;
        const uint32_t db = sb + 32768u + (uint32_t)(buf * 16384) + drow + dx;
#pragma unroll
        for (int t = 0; t < 4; t++) {
            cp16(da + t * 32 * 128, ap + (size_t)t * 32 * DD);
            cp16(db + t * 32 * 128, bp + (size_t)t * 32 * DD);
        }
        CP_COMMIT();
    };

    issue(0);
    for (int s = 0; s < NSTAGE; s++) {
        if (s + 1 < NSTAGE) { issue(s + 1); CP_WAIT1(); }
        else                { CP_WAIT0(); }
        __syncthreads();

        const uint32_t abase = sb + (uint32_t)((s & 1) * 16384);
        const uint32_t bbase = sb + 32768u + (uint32_t)((s & 1) * 16384);
#pragma unroll
        for (int kk = 0; kk < 4; kk++) {
            const uint32_t kb = (uint32_t)(kk * 32);
            uint32_t bf[4][2];
#pragma unroll
            for (int jj = 0; jj < 2; jj++) {
                uint32_t t4[4];
                ldsm4(t4, bbase + brow[jj] + ((kb + lcol) ^ bmask[jj]));
                bf[jj * 2][0]     = t4[0];
                bf[jj * 2 + 1][0] = t4[1];
                bf[jj * 2][1]     = t4[2];
                bf[jj * 2 + 1][1] = t4[3];
            }
            uint32_t af[4][4];
#pragma unroll
            for (int i = 0; i < 4; i++)
                ldsm4(af[i], abase + arow[i] + ((kb + lcol) ^ amask[i]));
#pragma unroll
            for (int i = 0; i < 4; i++)
#pragma unroll
                for (int j = 0; j < 4; j++)
                    mma16816(d[i][j], af[i], bf[j]);
        }
        __syncthreads();
    }

    // --- stage C into smem (stride 132 to dodge bank conflicts) ---
    float* Cst = (float*)sgen;
    {
        const int qr = lane >> 2;
        const int qc = (lane & 3) * 2;
#pragma unroll
        for (int i = 0; i < 4; i++) {
#pragma unroll
            for (int j = 0; j < 4; j++) {
                int r0 = wm + i * 16 + qr;
                int cc = wn + j * 8 + qc;
                *(float2*)&Cst[r0 * 132 + cc]       = make_float2(d[i][j][0], d[i][j][1]);
                *(float2*)&Cst[(r0 + 8) * 132 + cc] = make_float2(d[i][j][2], d[i][j][3]);
            }
        }
    }
    __syncthreads();

    // --- per-row epilogue: LoRA add + RoPE/scatter ---
    {
        const int row = tid >> 1;
        const int ch  = (tid & 1) * 64;
        const int m   = m0 + row;
        const int b   = m >> 11, sq = m & 2047;
        const float ps = psc[b];
        const float* aLp = is_o ? (g_loraO + (size_t)m * 16)
                                : (g_loraQKV + (size_t)m * 48 + mode * 16);
        float aLv[16];
#pragma unroll
        for (int r = 0; r < 16; r++) aLv[r] = aLp[r] * ps;

        const int h = n0 >> 7;
#pragma unroll
        for (int half = 0; half < 2; half++) {
            const int cb = ch + half * 32;
            float c[32];
#pragma unroll
            for (int j = 0; j < 32; j++) {
                float lora = 0.f;
#pragma unroll
                for (int r = 0; r < 16; r++) lora += aLv[r] * wBs[r * 128 + cb + j];
                c[j] = Cst[row * 132 + cb + j] + lora;
            }
            if (mode == 3) {
                float* dst = &Cout[(size_t)m * DD + n0 + cb];
#pragma unroll
                for (int j = 0; j < 32; j += 4)
                    *(float4*)(dst + j) = make_float4(c[j], c[j+1], c[j+2], c[j+3]);
            } else if (mode == 2) {
                float* dst = &g_V[(((size_t)(b * HH + h) * PSL) + PP + sq) * DH + cb];
#pragma unroll
                for (int j = 0; j < 32; j += 4)
                    *(float4*)(dst + j) = make_float4(c[j], c[j+1], c[j+2], c[j+3]);
            } else {
                float e[16], o[16];
#pragma unroll
                for (int p = 0; p < 16; p++) {
                    int dcol = cb + 2 * p;
                    float cz = fcos[sq * 64 + (dcol >> 1)];
                    float sz = fsin[sq * 64 + (dcol >> 1)];
                    float a = c[2 * p], bq = c[2 * p + 1];
                    e[p] = a * cz - bq * sz;
                    o[p] = a * sz + bq * cz;
                }
                if (mode == 0) {
                    float* dst = &g_Q[(((size_t)(b * HH + h) * SS) + sq) * DH + cb];
#pragma unroll
                    for (int p = 0; p < 16; p += 2)
                        *(float4*)(dst + 2 * p) = make_float4(e[p], o[p], e[p+1], o[p+1]);
                } else {
                    float* dst = &g_K[((size_t)(b * HH + h) * DH + cb) * PSL + PP + sq];
#pragma unroll
                    for (int p = 0; p < 16; p++) {
                        dst[(2 * p) * PSL]     = e[p];
                        dst[(2 * p + 1) * PSL] = o[p];
                    }
                }
            }
        }
    }
}

// ---------------------------------------------------------------------------
// Flash attention, fp32 SIMT, 64x64 tiles, online softmax (unchanged)
// ---------------------------------------------------------------------------
#define ATTN_SMEM ((64 * 128 + 128 * 68 + 64 * 68 + 64 * 3) * 4)

__global__ __launch_bounds__(256, 2)
void attn_kernel()
{
    extern __shared__ __align__(16) float sm[];
    float* Qs   = sm;                     // [64][128]
    float* Kst  = Qs + 64 * 128;          // [128][68] (Kt) aliased with Vs[64][128]
    float* Ss   = Kst + 128 * 68;         // [64][68]
    float* mrow = Ss + 64 * 68;
    float* lrow = mrow + 64;
    float* arow = lrow + 64;

    const int tid = threadIdx.x;
    const int bh  = blockIdx.y;           // b*16 + h
    const int i0  = blockIdx.x * 64;      // query tile start
    const int tx  = tid & 15, ty = tid >> 4;

    const float* Qb = g_Q + (size_t)bh * SS * DH;
    const float* Kb = g_K + (size_t)bh * DH * PSL;
    const float* Vb = g_V + (size_t)bh * PSL * DH;

    const float scl = 0.088388347648318447f;   // 1/sqrt(128)
    for (int idx = tid; idx < 64 * 32; idx += 256) {
        int rr = idx >> 5, c4 = idx & 31;
        float4 v = *(const float4*)&Qb[(size_t)(i0 + rr) * DH + c4 * 4];
        v.x *= scl; v.y *= scl; v.z *= scl; v.w *= scl;
        *(float4*)&Qs[rr * 128 + c4 * 4] = v;
    }
    if (tid < 64) { mrow[tid] = -1e30f; lrow[tid] = 0.f; }

    ull o2[4][4];
#pragma unroll
    for (int i = 0; i < 4; i++)
#pragma unroll
        for (int j = 0; j < 4; j++) o2[i][j] = 0ull;

    const int ntiles = 17 + (i0 >> 6);
    const int srow = tid >> 2, l4 = tid & 3;

    for (int t = 0; t < ntiles; t++) {
        const int j0 = t * 64;
        __syncthreads();   // protect aliased K/V buffer from previous iteration

        for (int idx = tid; idx < 128 * 16; idx += 256) {
            int dd = idx >> 4, j4 = idx & 15;
            float4 v = *(const float4*)&Kb[(size_t)dd * PSL + j0 + j4 * 4];
            *(float4*)&Kst[dd * 68 + j4 * 4] = v;
        }
        __syncthreads();

        ull s2[4][2];
#pragma unroll
        for (int i = 0; i < 4; i++) { s2[i][0] = 0ull; s2[i][1] = 0ull; }
#pragma unroll 8
        for (int kk = 0; kk < 128; kk++) {
            longlong2 bq = *(const longlong2*)&Kst[kk * 68 + tx * 4];
            const ull b0 = (ull)bq.x, b1 = (ull)bq.y;
#pragma unroll
            for (int i = 0; i < 4; i++) {
                float a = Qs[(ty * 4 + i) * 128 + kk];
                ull aa = pack2(a, a);
                ffma2(s2[i][0], aa, b0);
                ffma2(s2[i][1], aa, b1);
            }
        }

#pragma unroll
        for (int i = 0; i < 4; i++) {
            int jlim = PP + i0 + ty * 4 + i;
#pragma unroll
            for (int jj = 0; jj < 2; jj++) {
                float lo, hi;
                unpack2(lo, hi, s2[i][jj]);
                int j = j0 + tx * 4 + jj * 2;
                if (j > jlim)     lo = -1e30f;
                if (j + 1 > jlim) hi = -1e30f;
                Ss[(ty * 4 + i) * 68 + tx * 4 + jj * 2]     = lo;
                Ss[(ty * 4 + i) * 68 + tx * 4 + jj * 2 + 1] = hi;
            }
        }
        __syncthreads();

        {
            float* srp = &Ss[srow * 68 + l4 * 16];
            float mt = -1e30f;
#pragma unroll
            for (int cc = 0; cc < 16; cc++) mt = fmaxf(mt, srp[cc]);
            mt = fmaxf(mt, __shfl_xor_sync(0xffffffffu, mt, 1));
            mt = fmaxf(mt, __shfl_xor_sync(0xffffffffu, mt, 2));
            float mo = mrow[srow];
            float mn = fmaxf(mo, mt);
            float su = 0.f;
#pragma unroll
            for (int cc = 0; cc < 16; cc++) {
                float p = __expf(srp[cc] - mn);
                srp[cc] = p;
                su += p;
            }
            su += __shfl_xor_sync(0xffffffffu, su, 1);
            su += __shfl_xor_sync(0xffffffffu, su, 2);
            if (l4 == 0) {
                float al = __expf(mo - mn);
                lrow[srow] = lrow[srow] * al + su;
                mrow[srow] = mn;
                arow[srow] = al;
            }
        }
        __syncthreads();

        float* Vs = Kst;
        for (int idx = tid; idx < 64 * 32; idx += 256) {
            int rr = idx >> 5, c4 = idx & 31;
            *(float4*)&Vs[rr * 128 + c4 * 4] =
                *(const float4*)&Vb[(size_t)(j0 + rr) * DH + c4 * 4];
        }
        __syncthreads();

#pragma unroll
        for (int i = 0; i < 4; i++) {
            float al = arow[ty * 4 + i];
            ull af = pack2(al, al);
#pragma unroll
            for (int j = 0; j < 4; j++) fmul2(o2[i][j], af);
        }
#pragma unroll 4
        for (int jk = 0; jk < 64; jk++) {
            longlong2 v0 = *(const longlong2*)&Vs[jk * 128 + tx * 8];
            longlong2 v1 = *(const longlong2*)&Vs[jk * 128 + tx * 8 + 4];
            const ull b0 = (ull)v0.x, b1 = (ull)v0.y, b2 = (ull)v1.x, b3 = (ull)v1.y;
#pragma unroll
            for (int i = 0; i < 4; i++) {
                float p = Ss[(ty * 4 + i) * 68 + jk];
                ull pp = pack2(p, p);
                ffma2(o2[i][0], pp, b0);
                ffma2(o2[i][1], pp, b1);
                ffma2(o2[i][2], pp, b2);
                ffma2(o2[i][3], pp, b3);
            }
        }
    }

    const int b = bh >> 4, h = bh & 15;
#pragma unroll
    for (int i = 0; i < 4; i++) {
        int sq = i0 + ty * 4 + i;
        float inv = 1.0f / lrow[ty * 4 + i];
        float o[8];
#pragma unroll
        for (int j = 0; j < 4; j++) {
            unpack2(o[2 * j], o[2 * j + 1], o2[i][j]);
            o[2 * j] *= inv; o[2 * j + 1] *= inv;
        }
        float* dst = &g_attn[((size_t)b * SS + sq) * DD + h * DH + tx * 8];
        *(float4*)dst       = make_float4(o[0], o[1], o[2], o[3]);
        *(float4*)(dst + 4) = make_float4(o[4], o[5], o[6], o[7]);
    }
}

// ---------------------------------------------------------------------------
// Launch
// ---------------------------------------------------------------------------
extern "C" void kernel_launch(void* const* d_in, const int* in_sizes, int n_in,
                              void* d_out, int out_size)
{
    const float* x    = (const float*)d_in[0];
    const float* fcos = (const float*)d_in[1];
    const float* fsin = (const float*)d_in[2];
    // d_in[3] = mask (unused; causality computed analytically)
    const float* pk   = (const float*)d_in[4];
    const float* pv   = (const float*)d_in[5];
    const float* ps   = (const float*)d_in[6];
    const float* wq   = (const float*)d_in[7];
    const float* wk   = (const float*)d_in[8];
    const float* wv   = (const float*)d_in[9];
    const float* wo   = (const float*)d_in[10];
    const float* wqA  = (const float*)d_in[11];
    const float* wqB  = (const float*)d_in[12];
    const float* wkA  = (const float*)d_in[13];
    const float* wkB  = (const float*)d_in[14];
    const float* wvA  = (const float*)d_in[15];
    const float* wvB  = (const float*)d_in[16];
    const float* woA  = (const float*)d_in[17];
    const float* woB  = (const float*)d_in[18];
    float* out        = (float*)d_out;

    static void* sym_xhi = nullptr, *sym_xlo = nullptr;
    static void* sym_ahi = nullptr, *sym_alo = nullptr, *sym_attn = nullptr;
    if (!sym_xhi) {
        cudaGetSymbolAddress(&sym_xhi, g_xhi);
        cudaGetSymbolAddress(&sym_xlo, g_xlo);
        cudaGetSymbolAddress(&sym_ahi, g_ahi);
        cudaGetSymbolAddress(&sym_alo, g_alo);
        cudaGetSymbolAddress(&sym_attn, g_attn);
    }

    cudaFuncSetAttribute(attn_kernel, cudaFuncAttributeMaxDynamicSharedMemorySize,
                         ATTN_SMEM);
    cudaFuncSetAttribute(gemm_tc, cudaFuncAttributeMaxDynamicSharedMemorySize,
                         GEMM_SMEM);

    scatter_prev<<<(BB * PP * HH * (DH / 4) + 255) / 256, 256>>>(pk, pv);
    split4<<<(MM * DD / 4) / 256, 256>>>(x, (__nv_bfloat16*)sym_xhi,
                                         (__nv_bfloat16*)sym_xlo);
    split_w4<<<dim3((DD * DD / 4) / 256, 1, 4), 256>>>(wq, wk, wv, wo);
    lora_down_qkv<<<MM / 32, 256>>>(x, wqA, wkA, wvA);

    gemm_tc<<<dim3(DD / 128, MM / 128, 3), 256, GEMM_SMEM>>>(
        ps, fcos, fsin, wqB, wkB, wvB, nullptr, 0);

    attn_kernel<<<dim3(SS / 64, BB * HH), 256, ATTN_SMEM>>>();

    lora_down_o<<<MM / 32, 256>>>(woA);
    split4<<<(MM * DD / 4) / 256, 256>>>((const float*)sym_attn,
                                         (__nv_bfloat16*)sym_ahi,
                                         (__nv_bfloat16*)sym_alo);

    gemm_tc<<<dim3(DD / 128, MM / 128, 1), 256, GEMM_SMEM>>>(
        ps, fcos, fsin, woB, nullptr, nullptr, out, 1);
}

// round 8
// speedup vs baseline: 2.7929x; 1.8252x over previous
#include <cuda_runtime.h>
#include <cuda_bf16.h>
#include <cstdint>

typedef unsigned long long ull;

// Problem constants
#define BB   2
#define SS   2048
#define PP   1024
#define DD   2048
#define HH   16
#define DH   128
#define PSL  3072          // P + S
#define MM   4096          // B * S
#define LKS  4             // lora split-K factor

// ---------------------------------------------------------------------------
// Scratch (device globals; no allocation allowed in kernel_launch)
// ---------------------------------------------------------------------------
__device__ float g_attn[(size_t)MM * DD];             // [m, h*DH+d] fp32
__device__ float g_lqkv_part[LKS][(size_t)MM * 48];   // lora down partials (q|k|v)
__device__ float g_lo_part[LKS][(size_t)MM * 16];

// bf16 split operands
__device__ __nv_bfloat16 g_xhi[(size_t)MM * DD];
__device__ __nv_bfloat16 g_xlo[(size_t)MM * DD];
__device__ __nv_bfloat16 g_ahi[(size_t)MM * DD];
__device__ __nv_bfloat16 g_alo[(size_t)MM * DD];
__device__ __nv_bfloat16 g_whi[(size_t)4 * DD * DD];  // wq|wk|wv|wo
__device__ __nv_bfloat16 g_wlo[(size_t)4 * DD * DD];

// attention operands, bf16 hi/lo split
__device__ __nv_bfloat16 g_Qh[(size_t)BB * HH * SS * DH];   // [b,h,s,d] (pre-scaled)
__device__ __nv_bfloat16 g_Ql[(size_t)BB * HH * SS * DH];
__device__ __nv_bfloat16 g_Kh[(size_t)BB * HH * PSL * DH];  // [b,h,j,d]
__device__ __nv_bfloat16 g_Kl[(size_t)BB * HH * PSL * DH];
__device__ __nv_bfloat16 g_Vh[(size_t)BB * HH * PSL * DH];  // [b,h,j,d]
__device__ __nv_bfloat16 g_Vl[(size_t)BB * HH * PSL * DH];

// ---------------------------------------------------------------------------
// helpers
// ---------------------------------------------------------------------------
__device__ __forceinline__ uint32_t smem_to_u32(const void* smem_ptr) {
    uint32_t addr;
    asm("{ .reg .u64 tmp; cvta.to.shared.u64 tmp, %1; cvt.u32.u64 %0, tmp; }"
        : "=r"(addr) : "l"(smem_ptr));
    return addr;
}
__device__ __forceinline__ void cp16(uint32_t dst, const void* src) {
    asm volatile("cp.async.cg.shared.global [%0], [%1], 16;"
                 :: "r"(dst), "l"(src) : "memory");
}
#define CP_COMMIT() asm volatile("cp.async.commit_group;" ::: "memory")
#define CP_WAIT1()  asm volatile("cp.async.wait_group 1;" ::: "memory")
#define CP_WAIT0()  asm volatile("cp.async.wait_group 0;" ::: "memory")

__device__ __forceinline__ void ldsm4(uint32_t a[4], uint32_t addr) {
    asm volatile("ldmatrix.sync.aligned.m8n8.x4.shared.b16 {%0,%1,%2,%3}, [%4];"
        : "=r"(a[0]), "=r"(a[1]), "=r"(a[2]), "=r"(a[3]) : "r"(addr));
}
__device__ __forceinline__ void ldsm4t(uint32_t a[4], uint32_t addr) {
    asm volatile("ldmatrix.sync.aligned.m8n8.x4.trans.shared.b16 {%0,%1,%2,%3}, [%4];"
        : "=r"(a[0]), "=r"(a[1]), "=r"(a[2]), "=r"(a[3]) : "r"(addr));
}
__device__ __forceinline__ void mma16816(float d[4], const uint32_t a[4],
                                         const uint32_t b[2]) {
    asm volatile(
        "mma.sync.aligned.m16n8k16.row.col.f32.bf16.bf16.f32 "
        "{%0,%1,%2,%3}, {%4,%5,%6,%7}, {%8,%9}, {%0,%1,%2,%3};"
        : "+f"(d[0]), "+f"(d[1]), "+f"(d[2]), "+f"(d[3])
        : "r"(a[0]), "r"(a[1]), "r"(a[2]), "r"(a[3]), "r"(b[0]), "r"(b[1]));
}

__device__ __forceinline__ unsigned short bfu(float x) {
    return __bfloat16_as_ushort(__float2bfloat16(x));
}
// split two floats into packed bf16x2 hi and lo (residual)
__device__ __forceinline__ void bfsplit2(float a, float b, uint32_t& h, uint32_t& l) {
    __nv_bfloat16 ah = __float2bfloat16(a), bh = __float2bfloat16(b);
    float ar = a - __bfloat162float(ah);
    float br = b - __bfloat162float(bh);
    h = (uint32_t)__bfloat16_as_ushort(ah) | ((uint32_t)__bfloat16_as_ushort(bh) << 16);
    l = (uint32_t)bfu(ar) | ((uint32_t)bfu(br) << 16);
}
// split-store 32 consecutive floats as bf16 hi/lo (dst 16B-aligned)
__device__ __forceinline__ void store32_split(const float* v,
                                              __nv_bfloat16* dh, __nv_bfloat16* dl) {
    unsigned short hs[32], ls[32];
#pragma unroll
    for (int j = 0; j < 32; j++) {
        __nv_bfloat16 hb = __float2bfloat16(v[j]);
        float r = v[j] - __bfloat162float(hb);
        hs[j] = __bfloat16_as_ushort(hb);
        ls[j] = bfu(r);
    }
#pragma unroll
    for (int j = 0; j < 4; j++) {
        ((uint4*)dh)[j] = *(uint4*)&hs[j * 8];
        ((uint4*)dl)[j] = *(uint4*)&ls[j * 8];
    }
}

// ---------------------------------------------------------------------------
// fp32 -> bf16 hi/lo split kernels (x and weights)
// ---------------------------------------------------------------------------
__device__ __forceinline__ void bsplit4_store(float4 v, __nv_bfloat16* hi,
                                              __nv_bfloat16* lo, size_t i4)
{
    float a[4] = {v.x, v.y, v.z, v.w};
    unsigned short h[4], l[4];
#pragma unroll
    for (int j = 0; j < 4; j++) {
        __nv_bfloat16 hb = __float2bfloat16(a[j]);
        float r = a[j] - __bfloat162float(hb);
        h[j] = __bfloat16_as_ushort(hb);
        l[j] = bfu(r);
    }
    ((ushort4*)hi)[i4] = make_ushort4(h[0], h[1], h[2], h[3]);
    ((ushort4*)lo)[i4] = make_ushort4(l[0], l[1], l[2], l[3]);
}

__global__ __launch_bounds__(256)
void split4(const float* __restrict__ src, __nv_bfloat16* __restrict__ hi,
            __nv_bfloat16* __restrict__ lo)
{
    size_t i = (size_t)blockIdx.x * 256 + threadIdx.x;
    float4 v = ((const float4*)src)[i];
    bsplit4_store(v, hi, lo, i);
}

__global__ __launch_bounds__(256)
void split_w4(const float* __restrict__ w0, const float* __restrict__ w1,
              const float* __restrict__ w2, const float* __restrict__ w3)
{
    const int z = blockIdx.z;
    const float* src = (z == 0) ? w0 : ((z == 1) ? w1 : ((z == 2) ? w2 : w3));
    __nv_bfloat16* hi = g_whi + (size_t)z * DD * DD;
    __nv_bfloat16* lo = g_wlo + (size_t)z * DD * DD;
    size_t i = (size_t)blockIdx.x * 256 + threadIdx.x;
    float4 v = ((const float4*)src)[i];
    bsplit4_store(v, hi, lo, i);
}

// ---------------------------------------------------------------------------
// LoRA down-projections: split-K=4, thread = 4 rows x 3 cols (qkv) / 4x1 (o)
// ---------------------------------------------------------------------------
__global__ __launch_bounds__(256)
void lora_down_qkv(const float* __restrict__ x,
                   const float* __restrict__ wqA,
                   const float* __restrict__ wkA,
                   const float* __restrict__ wvA)
{
    __shared__ float xs[32][68];
    __shared__ float ws[32][48];
    const int tid = threadIdx.x;
    const int m0  = blockIdx.x * 64;
    const int kq  = blockIdx.y;
    const int cg  = tid & 15;
    const int rg  = tid >> 4;

    float acc[4][3];
#pragma unroll
    for (int i = 0; i < 4; i++)
#pragma unroll
        for (int j = 0; j < 3; j++) acc[i][j] = 0.f;

    const int srow = tid >> 2, seg = tid & 3;
    for (int k0 = kq * 512; k0 < kq * 512 + 512; k0 += 32) {
        const float* xp = &x[(size_t)(m0 + srow) * DD + k0 + seg * 8];
        float4 v0 = *(const float4*)xp;
        float4 v1 = *(const float4*)(xp + 4);
        const int sbk = seg * 8;
        xs[sbk + 0][srow] = v0.x; xs[sbk + 1][srow] = v0.y;
        xs[sbk + 2][srow] = v0.z; xs[sbk + 3][srow] = v0.w;
        xs[sbk + 4][srow] = v1.x; xs[sbk + 5][srow] = v1.y;
        xs[sbk + 6][srow] = v1.z; xs[sbk + 7][srow] = v1.w;
        for (int idx = tid; idx < 32 * 48; idx += 256) {
            int kk = idx / 48, c = idx % 48;
            const float* w = (c < 16) ? wqA : ((c < 32) ? wkA : wvA);
            ws[kk][c] = w[(size_t)(k0 + kk) * 16 + (c & 15)];
        }
        __syncthreads();
#pragma unroll
        for (int kk = 0; kk < 32; kk++) {
            float4 xv = *(const float4*)&xs[kk][rg * 4];
            float w0 = ws[kk][cg * 3 + 0];
            float w1 = ws[kk][cg * 3 + 1];
            float w2 = ws[kk][cg * 3 + 2];
            acc[0][0] += xv.x * w0; acc[0][1] += xv.x * w1; acc[0][2] += xv.x * w2;
            acc[1][0] += xv.y * w0; acc[1][1] += xv.y * w1; acc[1][2] += xv.y * w2;
            acc[2][0] += xv.z * w0; acc[2][1] += xv.z * w1; acc[2][2] += xv.z * w2;
            acc[3][0] += xv.w * w0; acc[3][1] += xv.w * w1; acc[3][2] += xv.w * w2;
        }
        __syncthreads();
    }
#pragma unroll
    for (int i = 0; i < 4; i++)
#pragma unroll
        for (int j = 0; j < 3; j++)
            g_lqkv_part[kq][(size_t)(m0 + rg * 4 + i) * 48 + cg * 3 + j] = acc[i][j];
}

__global__ __launch_bounds__(256)
void lora_down_o(const float* __restrict__ woA)
{
    __shared__ float xs[32][68];
    __shared__ float ws[32][16];
    const int tid = threadIdx.x;
    const int m0  = blockIdx.x * 64;
    const int kq  = blockIdx.y;
    const int cg  = tid & 15;
    const int rg  = tid >> 4;

    float acc[4] = {0.f, 0.f, 0.f, 0.f};
    const int srow = tid >> 2, seg = tid & 3;
    for (int k0 = kq * 512; k0 < kq * 512 + 512; k0 += 32) {
        const float* xp = &g_attn[(size_t)(m0 + srow) * DD + k0 + seg * 8];
        float4 v0 = *(const float4*)xp;
        float4 v1 = *(const float4*)(xp + 4);
        const int sbk = seg * 8;
        xs[sbk + 0][srow] = v0.x; xs[sbk + 1][srow] = v0.y;
        xs[sbk + 2][srow] = v0.z; xs[sbk + 3][srow] = v0.w;
        xs[sbk + 4][srow] = v1.x; xs[sbk + 5][srow] = v1.y;
        xs[sbk + 6][srow] = v1.z; xs[sbk + 7][srow] = v1.w;
        if (tid < 32 * 16 / 8) {
            // 512 entries, 32 threads... use strided loop instead
        }
        for (int idx = tid; idx < 32 * 16; idx += 256) {
            int kk = idx >> 4, c = idx & 15;
            ws[kk][c] = woA[(size_t)(k0 + kk) * 16 + c];
        }
        __syncthreads();
#pragma unroll
        for (int kk = 0; kk < 32; kk++) {
            float4 xv = *(const float4*)&xs[kk][rg * 4];
            float w0 = ws[kk][cg];
            acc[0] += xv.x * w0; acc[1] += xv.y * w0;
            acc[2] += xv.z * w0; acc[3] += xv.w * w0;
        }
        __syncthreads();
    }
#pragma unroll
    for (int i = 0; i < 4; i++)
        g_lo_part[kq][(size_t)(m0 + rg * 4 + i) * 16 + cg] = acc[i];
}

// ---------------------------------------------------------------------------
// scatter prev_key/prev_value into bf16 hi/lo attention layouts
// ---------------------------------------------------------------------------
__global__ void scatter_prev(const float* __restrict__ pk, const float* __restrict__ pv)
{
    int idx = blockIdx.x * blockDim.x + threadIdx.x;   // over B*P*H*(DH/4)
    if (idx >= BB * PP * HH * (DH / 4)) return;
    int d4 = idx & 31;
    int h  = (idx >> 5) & 15;
    int p  = (idx >> 9) & 1023;
    int b  = idx >> 19;

    size_t base = (((size_t)(b * HH + h) * PSL) + p) * DH + d4 * 4;
    float4 kq = *(const float4*)&pk[(size_t)idx * 4];
    float4 vv = *(const float4*)&pv[(size_t)idx * 4];
    bsplit4_store(kq, g_Kh + base, g_Kl + base, 0);
    bsplit4_store(vv, g_Vh + base, g_Vl + base, 0);
}

// ---------------------------------------------------------------------------
// HMMA GEMM: 128x128 CTA tile, bf16-split (3 virtual K passes), cp.async.
//   mode 0: q (LoRA+RoPE+scale -> Qh/Ql)   mode 1: k (LoRA+RoPE -> Kh/Kl)
//   mode 2: v (LoRA -> Vh/Vl)              mode 3: o (LoRA -> Cout fp32)
// ---------------------------------------------------------------------------
#define GEMM_SMEM (67584 + 8192 + 128)
#define NSTAGE 96

__global__ __launch_bounds__(256)
void gemm_tc(const float* __restrict__ psc,
             const float* __restrict__ fcos, const float* __restrict__ fsin,
             const float* __restrict__ Bq, const float* __restrict__ Bk,
             const float* __restrict__ Bv,
             float* __restrict__ Cout, int is_o)
{
    extern __shared__ __align__(128) char dsm[];
    const uint32_t smem_raw = smem_to_u32(dsm);
    const uint32_t sb = (smem_raw + 127) & ~127u;
    char* sgen = dsm + (sb - smem_raw);

    const int tid  = threadIdx.x;
    const int lane = tid & 31;
    const int w    = tid >> 5;
    const int mode = is_o ? 3 : blockIdx.z;
    const int m0   = blockIdx.y * 128;
    const int n0   = blockIdx.x * 128;

    const __nv_bfloat16* __restrict__ Ahi = is_o ? g_ahi : g_xhi;
    const __nv_bfloat16* __restrict__ Alo = is_o ? g_alo : g_xlo;
    const __nv_bfloat16* __restrict__ Bhi = g_whi + (size_t)mode * DD * DD;
    const __nv_bfloat16* __restrict__ Blo = g_wlo + (size_t)mode * DD * DD;

    // LoRA wB tile -> smem (region disjoint from mainloop tiles)
    float* wBs = (float*)(sgen + 67584);
    const float* wBp = (mode == 0 || mode == 3) ? Bq : ((mode == 1) ? Bk : Bv);
    for (int idx = tid; idx < 16 * 128; idx += 256)
        wBs[idx] = wBp[(idx >> 7) * DD + n0 + (idx & 127)];

    const int rb = tid >> 3;
    const int c8 = tid & 7;
    const uint32_t dx   = (uint32_t)((c8 ^ (rb & 7)) * 16);
    const uint32_t drow = (uint32_t)(rb * 128);

    const int wm = (w & 1) * 64;
    const int wn = (w >> 1) * 32;
    const int lrow = lane & 15;
    const uint32_t lcol = (uint32_t)((lane >> 4) * 16);
    uint32_t arow[4], amask[4], brow[2], bmask[2];
#pragma unroll
    for (int i = 0; i < 4; i++) {
        int rr = wm + i * 16 + lrow;
        arow[i] = (uint32_t)(rr * 128); amask[i] = (uint32_t)((rr & 7) * 16);
    }
#pragma unroll
    for (int jj = 0; jj < 2; jj++) {
        int rr = wn + jj * 16 + lrow;
        brow[jj] = (uint32_t)(rr * 128); bmask[jj] = (uint32_t)((rr & 7) * 16);
    }

    float d[4][4][4];
#pragma unroll
    for (int i = 0; i < 4; i++)
#pragma unroll
        for (int j = 0; j < 4; j++)
#pragma unroll
            for (int q = 0; q < 4; q++) d[i][j][q] = 0.f;

    auto issue = [&](int s) {
        const int buf = s & 1;
        const int ko  = (s & 31) << 6;
        const __nv_bfloat16* As = (s >= 64) ? Alo : Ahi;
        const __nv_bfloat16* Bs = (s >= 32 && s < 64) ? Blo : Bhi;
        const __nv_bfloat16* ap = As + (size_t)(m0 + rb) * DD + ko + c8 * 8;
        const __nv_bfloat16* bp = Bs + (size_t)(n0 + rb) * DD + ko + c8 * 8;
        const uint32_t da = sb + (uint32_t)(buf * 16384) + drow + dx;
        const uint32_t db = sb + 32768u + (uint32_t)(buf * 16384) + drow + dx;
#pragma unroll
        for (int t = 0; t < 4; t++) {
            cp16(da + t * 32 * 128, ap + (size_t)t * 32 * DD);
            cp16(db + t * 32 * 128, bp + (size_t)t * 32 * DD);
        }
        CP_COMMIT();
    };

    issue(0);
    for (int s = 0; s < NSTAGE; s++) {
        if (s + 1 < NSTAGE) { issue(s + 1); CP_WAIT1(); }
        else                { CP_WAIT0(); }
        __syncthreads();

        const uint32_t abase = sb + (uint32_t)((s & 1) * 16384);
        const uint32_t bbase = sb + 32768u + (uint32_t)((s & 1) * 16384);
#pragma unroll
        for (int kk = 0; kk < 4; kk++) {
            const uint32_t kb = (uint32_t)(kk * 32);
            uint32_t bf[4][2];
#pragma unroll
            for (int jj = 0; jj < 2; jj++) {
                uint32_t t4[4];
                ldsm4(t4, bbase + brow[jj] + ((kb + lcol) ^ bmask[jj]));
                bf[jj * 2][0]     = t4[0];
                bf[jj * 2 + 1][0] = t4[1];
                bf[jj * 2][1]     = t4[2];
                bf[jj * 2 + 1][1] = t4[3];
            }
            uint32_t af[4][4];
#pragma unroll
            for (int i = 0; i < 4; i++)
                ldsm4(af[i], abase + arow[i] + ((kb + lcol) ^ amask[i]));
#pragma unroll
            for (int i = 0; i < 4; i++)
#pragma unroll
                for (int j = 0; j < 4; j++)
                    mma16816(d[i][j], af[i], bf[j]);
        }
        __syncthreads();
    }

    // --- stage C into smem (stride 132) ---
    float* Cst = (float*)sgen;
    {
        const int qr = lane >> 2;
        const int qc = (lane & 3) * 2;
#pragma unroll
        for (int i = 0; i < 4; i++) {
#pragma unroll
            for (int j = 0; j < 4; j++) {
                int r0 = wm + i * 16 + qr;
                int cc = wn + j * 8 + qc;
                *(float2*)&Cst[r0 * 132 + cc]       = make_float2(d[i][j][0], d[i][j][1]);
                *(float2*)&Cst[(r0 + 8) * 132 + cc] = make_float2(d[i][j][2], d[i][j][3]);
            }
        }
    }
    __syncthreads();

    // --- per-row epilogue ---
    {
        const int row = tid >> 1;
        const int ch  = (tid & 1) * 64;
        const int m   = m0 + row;
        const int b   = m >> 11, sq = m & 2047;
        const float ps = psc[b];
        float aLv[16];
#pragma unroll
        for (int r = 0; r < 16; r++) {
            float sum;
            if (is_o) {
                size_t o = (size_t)m * 16 + r;
                sum = g_lo_part[0][o] + g_lo_part[1][o] + g_lo_part[2][o] + g_lo_part[3][o];
            } else {
                size_t o = (size_t)m * 48 + mode * 16 + r;
                sum = g_lqkv_part[0][o] + g_lqkv_part[1][o] + g_lqkv_part[2][o] + g_lqkv_part[3][o];
            }
            aLv[r] = sum * ps;
        }

        const int h = n0 >> 7;
        const float scl = 0.088388347648318447f;   // 1/sqrt(128)
#pragma unroll
        for (int half = 0; half < 2; half++) {
            const int cb = ch + half * 32;
            float c[32];
#pragma unroll
            for (int j = 0; j < 32; j++) {
                float lora = 0.f;
#pragma unroll
                for (int r = 0; r < 16; r++) lora += aLv[r] * wBs[r * 128 + cb + j];
                c[j] = Cst[row * 132 + cb + j] + lora;
            }
            if (mode == 3) {
                float* dst = &Cout[(size_t)m * DD + n0 + cb];
#pragma unroll
                for (int j = 0; j < 32; j += 4)
                    *(float4*)(dst + j) = make_float4(c[j], c[j+1], c[j+2], c[j+3]);
            } else if (mode == 2) {
                size_t off = (((size_t)(b * HH + h) * PSL) + PP + sq) * DH + cb;
                store32_split(c, g_Vh + off, g_Vl + off);
            } else {
                float v[32];
#pragma unroll
                for (int p = 0; p < 16; p++) {
                    int dcol = cb + 2 * p;
                    float cz = fcos[sq * 64 + (dcol >> 1)];
                    float sz = fsin[sq * 64 + (dcol >> 1)];
                    float a = c[2 * p], bq = c[2 * p + 1];
                    v[2 * p]     = a * cz - bq * sz;
                    v[2 * p + 1] = a * sz + bq * cz;
                }
                if (mode == 0) {
#pragma unroll
                    for (int j = 0; j < 32; j++) v[j] *= scl;
                    size_t off = (((size_t)(b * HH + h) * SS) + sq) * DH + cb;
                    store32_split(v, g_Qh + off, g_Ql + off);
                } else {
                    size_t off = (((size_t)(b * HH + h) * PSL) + PP + sq) * DH + cb;
                    store32_split(v, g_Kh + off, g_Kl + off);
                }
            }
        }
    }
}

// ---------------------------------------------------------------------------
// HMMA flash attention: 128-q CTA, 8 warps (16 q each), 64-key tiles,
// bf16 hi/lo split on Q/K and P/V, softmax fully in registers.
// smem: QH 0 | QL 32768 | stage s at 65536+s*65536: KH,KL,VH,VL (16KB each)
// ---------------------------------------------------------------------------
#define ATTN_SMEM (65536 + 2 * 65536)

__global__ __launch_bounds__(256, 1)
void attn_mma()
{
    extern __shared__ __align__(128) char smdyn[];
    const uint32_t sb = smem_to_u32(smdyn);

    const int tid  = threadIdx.x;
    const int lane = tid & 31;
    const int w    = tid >> 5;
    const int bh   = blockIdx.y;
    const int i0   = blockIdx.x * 128;

    const __nv_bfloat16* Qhp = g_Qh + ((size_t)bh * SS + i0) * DH;
    const __nv_bfloat16* Qlp = g_Ql + ((size_t)bh * SS + i0) * DH;
    const __nv_bfloat16* Khp = g_Kh + (size_t)bh * PSL * DH;
    const __nv_bfloat16* Klp = g_Kl + (size_t)bh * PSL * DH;
    const __nv_bfloat16* Vhp = g_Vh + (size_t)bh * PSL * DH;
    const __nv_bfloat16* Vlp = g_Vl + (size_t)bh * PSL * DH;

    // ---- Q tiles (hi+lo), one cp.async group ----
    {
        int row = tid >> 1, cg = tid & 1;
        const __nv_bfloat16* qh = Qhp + (size_t)row * DH;
        const __nv_bfloat16* ql = Qlp + (size_t)row * DH;
        uint32_t dst = sb + row * 256;
#pragma unroll
        for (int i = 0; i < 8; i++) {
            int c = cg * 8 + i;
            uint32_t so = (uint32_t)((c ^ (row & 7)) * 16);
            cp16(dst + so, qh + c * 8);
            cp16(dst + 32768 + so, ql + c * 8);
        }
    }
    CP_COMMIT();

    const int ntiles = 18 + (i0 >> 6);
    auto issue_kv = [&](int t) {
        int row = tid >> 2, cg = tid & 3, j0 = t * 64;
        size_t goff = (size_t)(j0 + row) * DH;
        uint32_t dst = sb + 65536u + (uint32_t)((t & 1) * 65536) + row * 256;
#pragma unroll
        for (int i = 0; i < 4; i++) {
            int c = cg * 4 + i;
            uint32_t so = (uint32_t)((c ^ (row & 7)) * 16);
            cp16(dst + so,          Khp + goff + c * 8);
            cp16(dst + 16384 + so,  Klp + goff + c * 8);
            cp16(dst + 32768 + so,  Vhp + goff + c * 8);
            cp16(dst + 49152 + so,  Vlp + goff + c * 8);
        }
        CP_COMMIT();
    };
    issue_kv(0);

    float o[16][4];
#pragma unroll
    for (int i = 0; i < 16; i++)
#pragma unroll
        for (int q = 0; q < 4; q++) o[i][q] = 0.f;
    float m0r = -1e30f, m1r = -1e30f, l0 = 0.f, l1 = 0.f;

    const int lrow = lane & 15;
    const int lh   = lane >> 4;
    const uint32_t qaddr = sb + (uint32_t)((w * 16 + lrow) * 256);
    const int qsw = (w * 16 + lrow) & 7;
    const int ksw = lrow & 7;
    const int lim0 = PP + i0 + w * 16 + (lane >> 2);

    for (int t = 0; t < ntiles; t++) {
        if (t + 1 < ntiles) { issue_kv(t + 1); CP_WAIT1(); }
        else                { CP_WAIT0(); }
        __syncthreads();

        const uint32_t KHb = sb + 65536u + (uint32_t)((t & 1) * 65536);

        // ---- S = Q K^T (3 split passes fused) ----
        float s[8][4];
#pragma unroll
        for (int na = 0; na < 8; na++)
#pragma unroll
            for (int q = 0; q < 4; q++) s[na][q] = 0.f;

#pragma unroll
        for (int kk = 0; kk < 8; kk++) {
            uint32_t afh[4], afl[4];
            uint32_t ca = (uint32_t)(((kk * 2 + lh) ^ qsw) * 16);
            ldsm4(afh, qaddr + ca);
            ldsm4(afl, qaddr + 32768 + ca);
            uint32_t ck = (uint32_t)(((kk * 2 + lh) ^ ksw) * 16);
#pragma unroll
            for (int nb = 0; nb < 4; nb++) {
                uint32_t raddr = KHb + (uint32_t)((nb * 16 + lrow) * 256) + ck;
                uint32_t tkh[4], tkl[4];
                ldsm4(tkh, raddr);
                ldsm4(tkl, raddr + 16384);
                uint32_t b0h[2] = {tkh[0], tkh[2]}, b1h[2] = {tkh[1], tkh[3]};
                uint32_t b0l[2] = {tkl[0], tkl[2]}, b1l[2] = {tkl[1], tkl[3]};
                mma16816(s[2 * nb],     afh, b0h);
                mma16816(s[2 * nb],     afh, b0l);
                mma16816(s[2 * nb],     afl, b0h);
                mma16816(s[2 * nb + 1], afh, b1h);
                mma16816(s[2 * nb + 1], afh, b1l);
                mma16816(s[2 * nb + 1], afl, b1h);
            }
        }

        // ---- mask (last two tiles only) ----
        const int j0 = t * 64;
        if (j0 + 63 > PP + i0) {
#pragma unroll
            for (int na = 0; na < 8; na++) {
                int j = j0 + na * 8 + (lane & 3) * 2;
                if (j > lim0)         s[na][0] = -1e30f;
                if (j + 1 > lim0)     s[na][1] = -1e30f;
                if (j > lim0 + 8)     s[na][2] = -1e30f;
                if (j + 1 > lim0 + 8) s[na][3] = -1e30f;
            }
        }

        // ---- online softmax (registers + shfl) ----
        float mt0 = -1e30f, mt1 = -1e30f;
#pragma unroll
        for (int na = 0; na < 8; na++) {
            mt0 = fmaxf(mt0, fmaxf(s[na][0], s[na][1]));
            mt1 = fmaxf(mt1, fmaxf(s[na][2], s[na][3]));
        }
        mt0 = fmaxf(mt0, __shfl_xor_sync(0xffffffffu, mt0, 1));
        mt0 = fmaxf(mt0, __shfl_xor_sync(0xffffffffu, mt0, 2));
        mt1 = fmaxf(mt1, __shfl_xor_sync(0xffffffffu, mt1, 1));
        mt1 = fmaxf(mt1, __shfl_xor_sync(0xffffffffu, mt1, 2));
        float mn0 = fmaxf(m0r, mt0), mn1 = fmaxf(m1r, mt1);
        float a0 = __expf(m0r - mn0), a1 = __expf(m1r - mn1);
        m0r = mn0; m1r = mn1;
        float s0 = 0.f, s1 = 0.f;
#pragma unroll
        for (int na = 0; na < 8; na++) {
            s[na][0] = __expf(s[na][0] - mn0); s0 += s[na][0];
            s[na][1] = __expf(s[na][1] - mn0); s0 += s[na][1];
            s[na][2] = __expf(s[na][2] - mn1); s1 += s[na][2];
            s[na][3] = __expf(s[na][3] - mn1); s1 += s[na][3];
        }
        s0 += __shfl_xor_sync(0xffffffffu, s0, 1);
        s0 += __shfl_xor_sync(0xffffffffu, s0, 2);
        s1 += __shfl_xor_sync(0xffffffffu, s1, 1);
        s1 += __shfl_xor_sync(0xffffffffu, s1, 2);
        l0 = l0 * a0 + s0;
        l1 = l1 * a1 + s1;
#pragma unroll
        for (int na = 0; na < 16; na++) {
            o[na][0] *= a0; o[na][1] *= a0;
            o[na][2] *= a1; o[na][3] *= a1;
        }

        // ---- O += P V (P from registers, 3 split passes) ----
        const uint32_t VHb = KHb + 32768u;
#pragma unroll
        for (int jj = 0; jj < 4; jj++) {
            uint32_t ph[4], pl[4];
            bfsplit2(s[2 * jj][0],     s[2 * jj][1],     ph[0], pl[0]);
            bfsplit2(s[2 * jj][2],     s[2 * jj][3],     ph[1], pl[1]);
            bfsplit2(s[2 * jj + 1][0], s[2 * jj + 1][1], ph[2], pl[2]);
            bfsplit2(s[2 * jj + 1][2], s[2 * jj + 1][3], ph[3], pl[3]);
#pragma unroll
            for (int db = 0; db < 8; db++) {
                uint32_t vaddr = VHb + (uint32_t)((jj * 16 + lrow) * 256)
                               + (uint32_t)(((db * 2 + lh) ^ ksw) * 16);
                uint32_t tvh[4], tvl[4];
                ldsm4t(tvh, vaddr);
                ldsm4t(tvl, vaddr + 16384);
                uint32_t bh0[2] = {tvh[0], tvh[1]}, bh1[2] = {tvh[2], tvh[3]};
                uint32_t bl0[2] = {tvl[0], tvl[1]}, bl1[2] = {tvl[2], tvl[3]};
                mma16816(o[2 * db],     ph, bh0);
                mma16816(o[2 * db],     pl, bh0);
                mma16816(o[2 * db],     ph, bl0);
                mma16816(o[2 * db + 1], ph, bh1);
                mma16816(o[2 * db + 1], pl, bh1);
                mma16816(o[2 * db + 1], ph, bl1);
            }
        }
        __syncthreads();
    }

    // ---- normalize + write (fp32 g_attn and bf16 hi/lo for O gemm) ----
    {
        float inv0 = 1.0f / l0, inv1 = 1.0f / l1;
        int q0 = i0 + w * 16 + (lane >> 2);
        int b = bh >> 4, h = bh & 15;
        size_t base0 = ((size_t)b * SS + q0) * DD + h * DH + (lane & 3) * 2;
        size_t base1 = base0 + (size_t)8 * DD;
#pragma unroll
        for (int na = 0; na < 16; na++) {
            size_t o0 = base0 + na * 8;
            size_t o1 = base1 + na * 8;
            float f0 = o[na][0] * inv0, f1 = o[na][1] * inv0;
            float f2 = o[na][2] * inv1, f3 = o[na][3] * inv1;
            *(float2*)&g_attn[o0] = make_float2(f0, f1);
            *(float2*)&g_attn[o1] = make_float2(f2, f3);
            uint32_t h2, l2;
            bfsplit2(f0, f1, h2, l2);
            *(uint32_t*)&g_ahi[o0] = h2;
            *(uint32_t*)&g_alo[o0] = l2;
            bfsplit2(f2, f3, h2, l2);
            *(uint32_t*)&g_ahi[o1] = h2;
            *(uint32_t*)&g_alo[o1] = l2;
        }
    }
}

// ---------------------------------------------------------------------------
// Launch
// ---------------------------------------------------------------------------
extern "C" void kernel_launch(void* const* d_in, const int* in_sizes, int n_in,
                              void* d_out, int out_size)
{
    const float* x    = (const float*)d_in[0];
    const float* fcos = (const float*)d_in[1];
    const float* fsin = (const float*)d_in[2];
    // d_in[3] = mask (unused; causality computed analytically)
    const float* pk   = (const float*)d_in[4];
    const float* pv   = (const float*)d_in[5];
    const float* ps   = (const float*)d_in[6];
    const float* wq   = (const float*)d_in[7];
    const float* wk   = (const float*)d_in[8];
    const float* wv   = (const float*)d_in[9];
    const float* wo   = (const float*)d_in[10];
    const float* wqA  = (const float*)d_in[11];
    const float* wqB  = (const float*)d_in[12];
    const float* wkA  = (const float*)d_in[13];
    const float* wkB  = (const float*)d_in[14];
    const float* wvA  = (const float*)d_in[15];
    const float* wvB  = (const float*)d_in[16];
    const float* woA  = (const float*)d_in[17];
    const float* woB  = (const float*)d_in[18];
    float* out        = (float*)d_out;

    static void* sym_xhi = nullptr, *sym_xlo = nullptr;
    if (!sym_xhi) {
        cudaGetSymbolAddress(&sym_xhi, g_xhi);
        cudaGetSymbolAddress(&sym_xlo, g_xlo);
    }

    cudaFuncSetAttribute(gemm_tc, cudaFuncAttributeMaxDynamicSharedMemorySize,
                         GEMM_SMEM);
    cudaFuncSetAttribute(attn_mma, cudaFuncAttributeMaxDynamicSharedMemorySize,
                         ATTN_SMEM);

    scatter_prev<<<(BB * PP * HH * (DH / 4) + 255) / 256, 256>>>(pk, pv);
    split4<<<(MM * DD / 4) / 256, 256>>>(x, (__nv_bfloat16*)sym_xhi,
                                         (__nv_bfloat16*)sym_xlo);
    split_w4<<<dim3((DD * DD / 4) / 256, 1, 4), 256>>>(wq, wk, wv, wo);
    lora_down_qkv<<<dim3(MM / 64, LKS), 256>>>(x, wqA, wkA, wvA);

    gemm_tc<<<dim3(DD / 128, MM / 128, 3), 256, GEMM_SMEM>>>(
        ps, fcos, fsin, wqB, wkB, wvB, nullptr, 0);

    attn_mma<<<dim3(SS / 128, BB * HH), 256, ATTN_SMEM>>>();

    lora_down_o<<<dim3(MM / 64, LKS), 256>>>(woA);

    gemm_tc<<<dim3(DD / 128, MM / 128, 1), 256, GEMM_SMEM>>>(
        ps, fcos, fsin, woB, nullptr, nullptr, out, 1);
}